// round 6
// baseline (speedup 1.0000x reference)
#include <cuda_runtime.h>
#include <cstdint>

// Problem constants (fixed by the dataset).
#define E_EDGES 8192u
#define N_NODES 4096u
#define TOTAL (1u << 26)         // E*E elements
#define KOUT 16384               // K*E output rows
#define NWORDS (1u << 20)        // 2^26 bits / 64

// ---------------- device scratch (static allocations only) ----------------
__device__ unsigned g_cnt_d[N_NODES];
__device__ unsigned g_deg[N_NODES];
__device__ unsigned g_off[N_NODES + 1];
__device__ unsigned g_cursor[N_NODES];
__device__ int g_adj[E_EDGES];
__device__ unsigned long long g_numneg;
__device__ unsigned g_T;                       // mantissa threshold, 0..2^23
__device__ unsigned long long g_bitmap[NWORDS]; // 8 MB kept-bitmap over t in [0, 2^26)
__device__ unsigned g_blockcnt[1024];
__device__ unsigned g_blockoff[1024];

// ------- threefry-2x32, key = (0, 42), partitionable layout -------
// Per element t: x = (hi(t)=0, lo(t)=t), bits = out0 ^ out1.
#define TF_ROUND(r) { x0 += x1; x1 = __funnelshift_l(x1, x1, (r)) ^ x0; }

__device__ __forceinline__ unsigned tf_bits(unsigned t) {
    const unsigned ks0 = 0u, ks1 = 42u, ks2 = 0x1BD11BDAu ^ 42u;
    unsigned x0 = 0u;            // counts_hi + ks0
    unsigned x1 = t + ks1;       // counts_lo + ks1
    TF_ROUND(13) TF_ROUND(15) TF_ROUND(26) TF_ROUND(6)
    x0 += ks1; x1 += ks2 + 1u;
    TF_ROUND(17) TF_ROUND(29) TF_ROUND(16) TF_ROUND(24)
    x0 += ks2; x1 += ks0 + 2u;
    TF_ROUND(13) TF_ROUND(15) TF_ROUND(26) TF_ROUND(6)
    x0 += ks0; x1 += ks1 + 3u;
    TF_ROUND(17) TF_ROUND(29) TF_ROUND(16) TF_ROUND(24)
    x0 += ks1; x1 += ks2 + 4u;
    TF_ROUND(13) TF_ROUND(15) TF_ROUND(26) TF_ROUND(6)
    x0 += ks2; x1 += ks0 + 5u;
    return x0 ^ x1;
}

// ---------------- setup kernels ----------------
__global__ void k_zero() {
    unsigned tid = blockIdx.x * blockDim.x + threadIdx.x;  // 2^20 threads
    g_bitmap[tid] = 0ull;
    if (tid < N_NODES) { g_cnt_d[tid] = 0u; g_deg[tid] = 0u; g_cursor[tid] = 0u; }
    if (tid == 0) g_numneg = 0ull;
}

__global__ void k_hist(const int* __restrict__ src, const int* __restrict__ dst) {
    unsigned e = blockIdx.x * blockDim.x + threadIdx.x;
    if (e < E_EDGES) {
        unsigned d = (unsigned)dst[e], s = (unsigned)src[e];
        if (d < N_NODES) atomicAdd(&g_cnt_d[d], 1u);   // range guard: never corrupt scratch
        if (s < N_NODES) atomicAdd(&g_deg[s], 1u);
    }
}

__global__ void k_scan_deg() {  // 1 block, 1024 threads, 4 elems/thread
    __shared__ unsigned s[1024];
    unsigned t = threadIdx.x;
    unsigned v[4], sum = 0;
#pragma unroll
    for (int k = 0; k < 4; k++) { v[k] = g_deg[t * 4 + k]; sum += v[k]; }
    s[t] = sum; __syncthreads();
    for (int d = 1; d < 1024; d <<= 1) {
        unsigned a = (t >= (unsigned)d) ? s[t - d] : 0u;
        __syncthreads();
        s[t] += a;
        __syncthreads();
    }
    unsigned excl = (t == 0) ? 0u : s[t - 1];
#pragma unroll
    for (int k = 0; k < 4; k++) { g_off[t * 4 + k] = excl; excl += v[k]; }
    if (t == 1023) g_off[N_NODES] = excl;
}

__global__ void k_fill(const int* __restrict__ src, const int* __restrict__ dst) {
    unsigned e = blockIdx.x * blockDim.x + threadIdx.x;
    if (e < E_EDGES) {
        unsigned s = (unsigned)src[e];
        if (s < N_NODES) {
            unsigned pos = atomicAdd(&g_cursor[s], 1u);
            unsigned slot = g_off[s] + pos;
            if (slot < E_EDGES) g_adj[slot] = dst[e];
        }
    }
}

// per-node: X_s = sum of cnt_d over the distinct set B(s) = {s} ∪ adj(s)
__global__ void k_rowcount() {
    unsigned s = blockIdx.x * blockDim.x + threadIdx.x;
    if (s >= N_NODES) return;
    unsigned o = g_off[s], e = g_off[s + 1];
    unsigned d = e - o;
    if (d == 0) return;  // no rows with this src
    unsigned X = g_cnt_d[s];
    for (unsigned a = o; a < e; a++) {
        int v = g_adj[a];
        if (v == (int)s) continue;
        bool dup = false;
        for (unsigned b = o; b < a; b++) if (g_adj[b] == v) { dup = true; break; }
        if (!dup && (unsigned)v < N_NODES) X += g_cnt_d[v];
    }
    atomicAdd(&g_numneg, (unsigned long long)d * (unsigned long long)(E_EDGES - X));
}

__global__ void k_thresh() {
    unsigned long long nn = g_numneg;
    unsigned long long ratio = nn >> 13;  // // E
    unsigned T;
    if (ratio == 0ull) {
        T = 1u << 23;                     // keep_prob = inf -> all pass
    } else {
        float p = __fdiv_rn(2.0f, (float)ratio);   // matches jnp float32 divide
        double pt = (double)p * 8388608.0;          // p * 2^23 (exact)
        double ct = ceil(pt);
        T = (ct >= 8388608.0) ? (1u << 23) : (unsigned)ct;
    }
    g_T = T;
}

// ---------------- main scan: 2^26 threefry evaluations ----------------
__device__ __forceinline__ void try_keep(unsigned t,
                                         const int* __restrict__ src,
                                         const int* __restrict__ dst) {
    unsigned i = t >> 13, j = t & (E_EDGES - 1u);
    int s = src[i];
    int dj = dst[j];
    if (dj == s) return;
    unsigned o = g_off[s], e = g_off[s + 1];
    for (unsigned k = o; k < e; k++)
        if (g_adj[k] == dj) return;
    atomicOr(&g_bitmap[t >> 6], 1ull << (t & 63u));
}

#define PER 8
__global__ void __launch_bounds__(256) k_main(const int* __restrict__ src,
                                              const int* __restrict__ dst) {
    unsigned T = g_T;
    unsigned base = (blockIdx.x * 256u + threadIdx.x) * PER;
#pragma unroll
    for (int u = 0; u < PER; u++) {
        unsigned c = base + u;
        unsigned m = tf_bits(c) >> 9;
        if (m < T) try_keep(c, src, dst);
    }
}

// ---------------- ordered compaction of bitmap ----------------
__global__ void k_count() {  // 1024 blocks x 256 threads, 4 words each
    __shared__ unsigned s[256];
    unsigned wbase = blockIdx.x * 1024u + threadIdx.x * 4u;
    unsigned c = 0;
#pragma unroll
    for (int k = 0; k < 4; k++) c += __popcll(g_bitmap[wbase + k]);
    s[threadIdx.x] = c; __syncthreads();
    for (int d = 128; d > 0; d >>= 1) {
        if (threadIdx.x < (unsigned)d) s[threadIdx.x] += s[threadIdx.x + d];
        __syncthreads();
    }
    if (threadIdx.x == 0) g_blockcnt[blockIdx.x] = s[0];
}

__global__ void k_scan_blk() {  // 1 block, 1024 threads
    __shared__ unsigned s[1024];
    unsigned t = threadIdx.x;
    unsigned v = g_blockcnt[t];
    s[t] = v; __syncthreads();
    for (int d = 1; d < 1024; d <<= 1) {
        unsigned a = (t >= (unsigned)d) ? s[t - d] : 0u;
        __syncthreads();
        s[t] += a;
        __syncthreads();
    }
    g_blockoff[t] = s[t] - v;  // exclusive prefix
}

// Output is written as FLOAT32 (metadata __output__ dtype hypothesis):
// node indices 0..4095 are exactly representable.
__global__ void k_out_init(const int* __restrict__ src, const int* __restrict__ dst,
                           float* __restrict__ out, int out_size) {
    unsigned q = blockIdx.x * blockDim.x + threadIdx.x;
    if (q < KOUT) {
        if ((int)q < out_size) out[q] = (float)src[0];            // pad rows -> src[0]
        if ((int)(KOUT + q) < out_size) out[KOUT + q] = (float)dst[0];  // pad cols -> dst[0]
    }
}

__global__ void k_emit(const int* __restrict__ src, const int* __restrict__ dst,
                       float* __restrict__ out, int out_size) {
    __shared__ unsigned s[256];
    unsigned t = threadIdx.x;
    unsigned wbase = blockIdx.x * 1024u + t * 4u;
    unsigned long long w[4];
    unsigned c = 0;
#pragma unroll
    for (int k = 0; k < 4; k++) { w[k] = g_bitmap[wbase + k]; c += __popcll(w[k]); }
    s[t] = c; __syncthreads();
    for (int d = 1; d < 256; d <<= 1) {
        unsigned a = (t >= (unsigned)d) ? s[t - d] : 0u;
        __syncthreads();
        s[t] += a;
        __syncthreads();
    }
    unsigned pos = g_blockoff[blockIdx.x] + s[t] - c;  // global exclusive prefix
    if (c == 0) return;
#pragma unroll
    for (int k = 0; k < 4; k++) {
        unsigned long long ww = w[k];
        unsigned wi = wbase + k;
        while (ww) {
            int b = __ffsll((long long)ww) - 1;
            unsigned tt = wi * 64u + (unsigned)b;
            if (pos < KOUT) {
                if ((int)pos < out_size) out[pos] = (float)src[tt >> 13];
                if ((int)(KOUT + pos) < out_size) out[KOUT + pos] = (float)dst[tt & (E_EDGES - 1u)];
            }
            pos++;
            ww &= ww - 1ull;
        }
    }
}

// ---------------- launch ----------------
extern "C" void kernel_launch(void* const* d_in, const int* in_sizes, int n_in,
                              void* d_out, int out_size) {
    // Robust input selection by element count. Candidate metadata orders:
    //   dict order:        [node_feature(262144), edge_src(8192), edge_dst(8192)]
    //   alphabetical:      [edge_dst(8192), edge_src(8192), node_feature(262144)]
    // In both, edge_src is d_in[1]; edge_dst flips between d_in[2] and d_in[0].
    const int* src;
    const int* dst;
    if (n_in >= 3 && in_sizes[0] == (int)E_EDGES) {
        dst = (const int*)d_in[0];   // alphabetical: edge_dst first
        src = (const int*)d_in[1];
    } else {
        src = (const int*)d_in[1];   // dict order: node_feature first
        dst = (const int*)d_in[2];
    }
    float* out = (float*)d_out;

    k_zero<<<NWORDS / 512, 512>>>();
    k_hist<<<E_EDGES / 256, 256>>>(src, dst);
    k_scan_deg<<<1, 1024>>>();
    k_fill<<<E_EDGES / 256, 256>>>(src, dst);
    k_rowcount<<<N_NODES / 256, 256>>>();
    k_thresh<<<1, 1>>>();
    k_main<<<TOTAL / (256 * PER), 256>>>(src, dst);
    k_count<<<1024, 256>>>();
    k_scan_blk<<<1, 1024>>>();
    k_out_init<<<KOUT / 256, 256>>>(src, dst, out, out_size);
    k_emit<<<1024, 256>>>(src, dst, out, out_size);
}